// round 2
// baseline (speedup 1.0000x reference)
#include <cuda_runtime.h>
#include <cuda_bf16.h>
#include <math.h>

#define NUM_CLASSES 13
#define C1 (NUM_CLASSES + 1)          // 14
#define ROWS 1600000                  // 32*1000*50
#define TPB 256
#define NBLK (ROWS / TPB)             // 6250 exactly
#define W_CLASS 1.0
#define W_DOA   2.0

struct Part { float ce, ab, ct; };
__device__ Part g_part[NBLK];

__global__ __launch_bounds__(TPB)
void loss_main_kernel(const float* __restrict__ pred_logits,
                      const float* __restrict__ pred_doa,
                      const float* __restrict__ target_doa,
                      const float* __restrict__ empty_weight,
                      const int*   __restrict__ target_classes) {
    __shared__ float s_log[TPB * C1];     // 14336 B
    __shared__ float s_pd[TPB * 3];       // 3072 B
    __shared__ float s_td[TPB * 3];       // 3072 B

    const int tid = threadIdx.x;
    const size_t row0 = (size_t)blockIdx.x * TPB;

    // ---- cooperative float4 staging (all tiles are 16B-aligned: 14336/3072 per block) ----
    {
        const float4* src = reinterpret_cast<const float4*>(pred_logits + row0 * C1);
        float4* dst = reinterpret_cast<float4*>(s_log);
        #pragma unroll
        for (int i = tid; i < TPB * C1 / 4; i += TPB) dst[i] = __ldg(src + i);
    }
    {
        const float4* sp = reinterpret_cast<const float4*>(pred_doa + row0 * 3);
        const float4* st = reinterpret_cast<const float4*>(target_doa + row0 * 3);
        float4* dp = reinterpret_cast<float4*>(s_pd);
        float4* dt = reinterpret_cast<float4*>(s_td);
        #pragma unroll
        for (int i = tid; i < TPB * 3 / 4; i += TPB) { dp[i] = __ldg(sp + i); dt[i] = __ldg(st + i); }
    }
    const int tgt = __ldg(target_classes + row0 + tid);
    __syncthreads();

    // ---- per-row compute from smem ----
    float v[C1];
    #pragma unroll
    for (int j = 0; j < C1; j++) v[j] = s_log[tid * C1 + j];

    float m = v[0];
    #pragma unroll
    for (int j = 1; j < C1; j++) m = fmaxf(m, v[j]);
    float s = 0.0f;
    #pragma unroll
    for (int j = 0; j < C1; j++) s += expf(v[j] - m);
    float ce_w = __ldg(empty_weight + tgt) * (logf(s) + m - v[tgt]);

    float asum = 0.0f, cnt = 0.0f;
    if (tgt != NUM_CLASSES) {
        asum = fabsf(s_pd[tid * 3 + 0] - s_td[tid * 3 + 0])
             + fabsf(s_pd[tid * 3 + 1] - s_td[tid * 3 + 1])
             + fabsf(s_pd[tid * 3 + 2] - s_td[tid * 3 + 2]);
        cnt = 1.0f;
    }

    // ---- block reduction ----
    #pragma unroll
    for (int off = 16; off > 0; off >>= 1) {
        ce_w += __shfl_down_sync(0xFFFFFFFFu, ce_w, off);
        asum += __shfl_down_sync(0xFFFFFFFFu, asum, off);
        cnt  += __shfl_down_sync(0xFFFFFFFFu, cnt,  off);
    }
    __shared__ float r_ce[8], r_ab[8], r_ct[8];
    const int lane = tid & 31, wid = tid >> 5;
    if (lane == 0) { r_ce[wid] = ce_w; r_ab[wid] = asum; r_ct[wid] = cnt; }
    __syncthreads();
    if (wid == 0) {
        ce_w = (lane < 8) ? r_ce[lane] : 0.0f;
        asum = (lane < 8) ? r_ab[lane] : 0.0f;
        cnt  = (lane < 8) ? r_ct[lane] : 0.0f;
        #pragma unroll
        for (int off = 4; off > 0; off >>= 1) {
            ce_w += __shfl_down_sync(0xFFFFFFFFu, ce_w, off);
            asum += __shfl_down_sync(0xFFFFFFFFu, asum, off);
            cnt  += __shfl_down_sync(0xFFFFFFFFu, cnt,  off);
        }
        if (lane == 0) {
            Part p; p.ce = ce_w; p.ab = asum; p.ct = cnt;
            g_part[blockIdx.x] = p;      // unconditional write: no reset kernel needed
        }
    }
}

__global__ __launch_bounds__(TPB)
void finalize_kernel(float* __restrict__ out) {
    const int tid = threadIdx.x;
    double ce = 0.0, ab = 0.0, ct = 0.0;
    for (int i = tid; i < NBLK; i += TPB) {
        Part p = g_part[i];
        ce += p.ce; ab += p.ab; ct += p.ct;
    }
    #pragma unroll
    for (int off = 16; off > 0; off >>= 1) {
        ce += __shfl_down_sync(0xFFFFFFFFu, ce, off);
        ab += __shfl_down_sync(0xFFFFFFFFu, ab, off);
        ct += __shfl_down_sync(0xFFFFFFFFu, ct, off);
    }
    __shared__ double r_ce[8], r_ab[8], r_ct[8];
    const int lane = tid & 31, wid = tid >> 5;
    if (lane == 0) { r_ce[wid] = ce; r_ab[wid] = ab; r_ct[wid] = ct; }
    __syncthreads();
    if (tid == 0) {
        ce = 0.0; ab = 0.0; ct = 0.0;
        #pragma unroll
        for (int w = 0; w < 8; w++) { ce += r_ce[w]; ab += r_ab[w]; ct += r_ct[w]; }
        double loss_class = ce / (double)ROWS;
        double n_elems = ct * 3.0;
        double loss_doa = (n_elems > 0.0) ? (ab / fmax(n_elems, 1.0)) : 0.0;
        out[0] = (float)(W_CLASS * loss_class + W_DOA * loss_doa);
    }
}

extern "C" void kernel_launch(void* const* d_in, const int* in_sizes, int n_in,
                              void* d_out, int out_size) {
    const float* pred_logits    = (const float*)d_in[0];
    const float* pred_doa       = (const float*)d_in[1];
    const float* target_doa     = (const float*)d_in[2];
    const float* empty_weight   = (const float*)d_in[3];
    const int*   target_classes = (const int*)d_in[4];
    float* out = (float*)d_out;

    loss_main_kernel<<<NBLK, TPB>>>(pred_logits, pred_doa, target_doa,
                                    empty_weight, target_classes);
    finalize_kernel<<<1, TPB>>>(out);
}

// round 3
// speedup vs baseline: 1.1484x; 1.1484x over previous
#include <cuda_runtime.h>
#include <cuda_bf16.h>
#include <math.h>

#define NUM_CLASSES 13
#define C1 (NUM_CLASSES + 1)          // 14
#define ROWS 1600000                  // 32*1000*50
#define TPB 256
#define NBLK (ROWS / TPB)             // 6250 exactly
#define W_CLASS 1.0
#define W_DOA   2.0

// zero-initialized device globals; the LAST block of each launch resets them
// back to zero, so every graph replay starts from the same state.
__device__ double g_acc[3];
__device__ unsigned int g_ticket;

__global__ __launch_bounds__(TPB)
void loss_fused_kernel(const float* __restrict__ pred_logits,
                       const float* __restrict__ pred_doa,
                       const float* __restrict__ target_doa,
                       const float* __restrict__ empty_weight,
                       const int*   __restrict__ target_classes,
                       float* __restrict__ out) {
    __shared__ float s_log[TPB * C1];     // 14336 B
    __shared__ float s_pd[TPB * 3];       // 3072 B
    __shared__ float s_td[TPB * 3];       // 3072 B

    const int tid = threadIdx.x;
    const size_t row0 = (size_t)blockIdx.x * TPB;

    // ---- cooperative float4 staging (tiles are 16B-aligned: 14336/3072 per block) ----
    {
        const float4* src = reinterpret_cast<const float4*>(pred_logits + row0 * C1);
        float4* dst = reinterpret_cast<float4*>(s_log);
        #pragma unroll
        for (int i = tid; i < TPB * C1 / 4; i += TPB) dst[i] = __ldg(src + i);
    }
    {
        const float4* sp = reinterpret_cast<const float4*>(pred_doa + row0 * 3);
        const float4* st = reinterpret_cast<const float4*>(target_doa + row0 * 3);
        float4* dp = reinterpret_cast<float4*>(s_pd);
        float4* dt = reinterpret_cast<float4*>(s_td);
        #pragma unroll
        for (int i = tid; i < TPB * 3 / 4; i += TPB) { dp[i] = __ldg(sp + i); dt[i] = __ldg(st + i); }
    }
    const int tgt = __ldg(target_classes + row0 + tid);
    __syncthreads();

    // ---- per-row compute from smem ----
    float v[C1];
    #pragma unroll
    for (int j = 0; j < C1; j++) v[j] = s_log[tid * C1 + j];

    float m = v[0];
    #pragma unroll
    for (int j = 1; j < C1; j++) m = fmaxf(m, v[j]);
    float s = 0.0f;
    #pragma unroll
    for (int j = 0; j < C1; j++) s += expf(v[j] - m);
    float ce_w = __ldg(empty_weight + tgt) * (logf(s) + m - v[tgt]);

    float asum = 0.0f, cnt = 0.0f;
    if (tgt != NUM_CLASSES) {
        asum = fabsf(s_pd[tid * 3 + 0] - s_td[tid * 3 + 0])
             + fabsf(s_pd[tid * 3 + 1] - s_td[tid * 3 + 1])
             + fabsf(s_pd[tid * 3 + 2] - s_td[tid * 3 + 2]);
        cnt = 1.0f;
    }

    // ---- block reduction ----
    #pragma unroll
    for (int off = 16; off > 0; off >>= 1) {
        ce_w += __shfl_down_sync(0xFFFFFFFFu, ce_w, off);
        asum += __shfl_down_sync(0xFFFFFFFFu, asum, off);
        cnt  += __shfl_down_sync(0xFFFFFFFFu, cnt,  off);
    }
    __shared__ float r_ce[8], r_ab[8], r_ct[8];
    __shared__ bool s_last;
    const int lane = tid & 31, wid = tid >> 5;
    if (lane == 0) { r_ce[wid] = ce_w; r_ab[wid] = asum; r_ct[wid] = cnt; }
    __syncthreads();

    if (tid == 0) {
        float tce = 0.0f, tab = 0.0f, tct = 0.0f;
        #pragma unroll
        for (int w = 0; w < 8; w++) { tce += r_ce[w]; tab += r_ab[w]; tct += r_ct[w]; }
        atomicAdd(&g_acc[0], (double)tce);
        atomicAdd(&g_acc[1], (double)tab);
        atomicAdd(&g_acc[2], (double)tct);
        __threadfence();
        unsigned int ticket = atomicAdd(&g_ticket, 1u);
        s_last = (ticket == NBLK - 1);
    }
    __syncthreads();

    // ---- last block finalizes and resets state for the next graph replay ----
    if (s_last && tid == 0) {
        double ce = g_acc[0], ab = g_acc[1], ct = g_acc[2];
        double loss_class = ce / (double)ROWS;
        double n_elems = ct * 3.0;
        double loss_doa = (n_elems > 0.0) ? (ab / fmax(n_elems, 1.0)) : 0.0;
        out[0] = (float)(W_CLASS * loss_class + W_DOA * loss_doa);
        g_acc[0] = 0.0; g_acc[1] = 0.0; g_acc[2] = 0.0;
        __threadfence();
        g_ticket = 0u;
    }
}

extern "C" void kernel_launch(void* const* d_in, const int* in_sizes, int n_in,
                              void* d_out, int out_size) {
    const float* pred_logits    = (const float*)d_in[0];
    const float* pred_doa       = (const float*)d_in[1];
    const float* target_doa     = (const float*)d_in[2];
    const float* empty_weight   = (const float*)d_in[3];
    const int*   target_classes = (const int*)d_in[4];
    float* out = (float*)d_out;

    loss_fused_kernel<<<NBLK, TPB>>>(pred_logits, pred_doa, target_doa,
                                     empty_weight, target_classes, out);
}

// round 5
// speedup vs baseline: 1.5478x; 1.3478x over previous
#include <cuda_runtime.h>
#include <cuda_bf16.h>
#include <math.h>
#include <stdint.h>

#define NUM_CLASSES 13
#define C1 14                    // NUM_CLASSES+1
#define ROWS 1600000             // 32*1000*50
#define TPB 256
#define TPT 5                    // tiles per block
#define GRID (ROWS / (TPB * TPT))   // 1250
#define LOG4 (TPB * C1 / 4)      // 896 float4 per logit tile
#define DOA4 (TPB * 3 / 4)       // 192 float4 per doa tile
#define W_CLASS 1.0
#define W_DOA   2.0

__device__ double g_acc[3];
__device__ unsigned int g_ticket;

__device__ __forceinline__ unsigned int smem_u32(const void* p) {
    return (unsigned int)__cvta_generic_to_shared(p);
}
__device__ __forceinline__ void cpa16(unsigned int d, const void* s) {
    asm volatile("cp.async.cg.shared.global [%0], [%1], 16;" :: "r"(d), "l"(s));
}
__device__ __forceinline__ void cp_commit() {
    asm volatile("cp.async.commit_group;");
}
template<int N> __device__ __forceinline__ void cp_wait() {
    asm volatile("cp.async.wait_group %0;" :: "n"(N));
}

__global__ __launch_bounds__(TPB)
void loss_fused_kernel(const float* __restrict__ pred_logits,
                       const float* __restrict__ pred_doa,
                       const float* __restrict__ target_doa,
                       const float* __restrict__ empty_weight,
                       const int*   __restrict__ target_classes,
                       float* __restrict__ out) {
    __shared__ float s_log[2][TPB * C1];   // 2 x 14336 B
    __shared__ float s_pd[2][TPB * 3];     // 2 x 3072 B
    __shared__ float s_td[2][TPB * 3];
    __shared__ float s_ew[C1];
    __shared__ float r_ce[8], r_ab[8], r_ct[8];
    __shared__ bool  s_last;

    const int tid = threadIdx.x;
    const int base = blockIdx.x * TPT;     // first tile of this block

    if (tid < C1) s_ew[tid] = empty_weight[tid];

    // ---- cp.async issue for one tile into one buffer ----
    auto issue = [&](int buf, int tile) {
        const size_t r0 = (size_t)tile * TPB;
        const float4* gl = reinterpret_cast<const float4*>(pred_logits + r0 * C1);
        const float4* gp = reinterpret_cast<const float4*>(pred_doa + r0 * 3);
        const float4* gt = reinterpret_cast<const float4*>(target_doa + r0 * 3);
        unsigned int dl = smem_u32(&s_log[buf][0]);
        unsigned int dp = smem_u32(&s_pd[buf][0]);
        unsigned int dt = smem_u32(&s_td[buf][0]);
        cpa16(dl + (unsigned int)(tid)        * 16u, gl + tid);
        cpa16(dl + (unsigned int)(tid + 256)  * 16u, gl + tid + 256);
        cpa16(dl + (unsigned int)(tid + 512)  * 16u, gl + tid + 512);
        if (tid < LOG4 - 768)                                   // 128
            cpa16(dl + (unsigned int)(tid + 768) * 16u, gl + tid + 768);
        if (tid < DOA4) {                                        // 192
            cpa16(dp + (unsigned int)tid * 16u, gp + tid);
            cpa16(dt + (unsigned int)tid * 16u, gt + tid);
        }
    };

    // ---- prologue: prefetch tiles 0 and 1 ----
    issue(0, base);     cp_commit();
    issue(1, base + 1); cp_commit();

    int tg_cur = __ldg(target_classes + (size_t)base * TPB + tid);

    float acc_ce = 0.0f, acc_ab = 0.0f, acc_ct = 0.0f;

    #pragma unroll
    for (int k = 0; k < TPT; k++) {
        const int buf = k & 1;
        int tg_next = 0;
        if (k + 1 < TPT)
            tg_next = __ldg(target_classes + (size_t)(base + k + 1) * TPB + tid);

        cp_wait<1>();            // tile k's copies complete
        __syncthreads();

        // ---- compute tile k from smem (static register indexing only) ----
        const float2* rp = reinterpret_cast<const float2*>(&s_log[buf][tid * C1]);
        float v[C1];
        #pragma unroll
        for (int j = 0; j < C1 / 2; j++) {
            float2 p = rp[j];
            v[2 * j] = p.x; v[2 * j + 1] = p.y;
        }
        float m01 = fmaxf(v[0], v[1]),   m23 = fmaxf(v[2], v[3]);
        float m45 = fmaxf(v[4], v[5]),   m67 = fmaxf(v[6], v[7]);
        float m89 = fmaxf(v[8], v[9]),   mab = fmaxf(v[10], v[11]);
        float mcd = fmaxf(v[12], v[13]);
        float m = fmaxf(fmaxf(fmaxf(m01, m23), fmaxf(m45, m67)),
                        fmaxf(fmaxf(m89, mab), mcd));
        float s = 0.0f;
        #pragma unroll
        for (int j = 0; j < C1; j++) s += __expf(v[j] - m);
        float vt = s_log[buf][tid * C1 + tg_cur];       // single dynamic LDS
        acc_ce += s_ew[tg_cur] * (__logf(s) + m - vt);

        if (tg_cur != NUM_CLASSES) {
            acc_ab += fabsf(s_pd[buf][tid * 3 + 0] - s_td[buf][tid * 3 + 0])
                    + fabsf(s_pd[buf][tid * 3 + 1] - s_td[buf][tid * 3 + 1])
                    + fabsf(s_pd[buf][tid * 3 + 2] - s_td[buf][tid * 3 + 2]);
            acc_ct += 1.0f;
        }
        __syncthreads();         // everyone done reading buf before refill

        if (k + 2 < TPT) issue(buf, base + k + 2);
        cp_commit();             // commit (possibly empty) to keep group counts aligned
        tg_cur = tg_next;
    }

    // ---- single block reduction ----
    #pragma unroll
    for (int off = 16; off > 0; off >>= 1) {
        acc_ce += __shfl_down_sync(0xFFFFFFFFu, acc_ce, off);
        acc_ab += __shfl_down_sync(0xFFFFFFFFu, acc_ab, off);
        acc_ct += __shfl_down_sync(0xFFFFFFFFu, acc_ct, off);
    }
    const int lane = tid & 31, wid = tid >> 5;
    if (lane == 0) { r_ce[wid] = acc_ce; r_ab[wid] = acc_ab; r_ct[wid] = acc_ct; }
    __syncthreads();

    if (tid == 0) {
        float tce = 0.0f, tab = 0.0f, tct = 0.0f;
        #pragma unroll
        for (int w = 0; w < 8; w++) { tce += r_ce[w]; tab += r_ab[w]; tct += r_ct[w]; }
        atomicAdd(&g_acc[0], (double)tce);
        atomicAdd(&g_acc[1], (double)tab);
        atomicAdd(&g_acc[2], (double)tct);
        __threadfence();
        unsigned int ticket = atomicAdd(&g_ticket, 1u);
        s_last = (ticket == GRID - 1);
    }
    __syncthreads();

    // ---- last block finalizes and resets state for the next graph replay ----
    if (s_last && tid == 0) {
        double ce = g_acc[0], ab = g_acc[1], ct = g_acc[2];
        double loss_class = ce / (double)ROWS;
        double n_elems = ct * 3.0;
        double loss_doa = (n_elems > 0.0) ? (ab / fmax(n_elems, 1.0)) : 0.0;
        out[0] = (float)(W_CLASS * loss_class + W_DOA * loss_doa);
        g_acc[0] = 0.0; g_acc[1] = 0.0; g_acc[2] = 0.0;
        __threadfence();
        g_ticket = 0u;
    }
}

extern "C" void kernel_launch(void* const* d_in, const int* in_sizes, int n_in,
                              void* d_out, int out_size) {
    const float* pred_logits    = (const float*)d_in[0];
    const float* pred_doa       = (const float*)d_in[1];
    const float* target_doa     = (const float*)d_in[2];
    const float* empty_weight   = (const float*)d_in[3];
    const int*   target_classes = (const int*)d_in[4];
    float* out = (float*)d_out;

    loss_fused_kernel<<<GRID, TPB>>>(pred_logits, pred_doa, target_doa,
                                     empty_weight, target_classes, out);
}

// round 6
// speedup vs baseline: 1.5614x; 1.0088x over previous
#include <cuda_runtime.h>
#include <cuda_bf16.h>
#include <math.h>
#include <stdint.h>

#define NUM_CLASSES 13
#define C1 14                       // NUM_CLASSES+1
#define ROWS 1600000                // 32*1000*50
#define TPB 256
#define TPT 5                       // logit tiles per block
#define GRID (ROWS / (TPB * TPT))   // 1250
#define LOG4 (TPB * C1 / 4)         // 896 float4 per logit tile
#define DOA4_BLK (TPB * TPT * 3 / 4) // 960 float4 per block (per doa array)
#define W_CLASS 1.0
#define W_DOA   2.0

__device__ double g_acc[3];
__device__ unsigned int g_ticket;

__device__ __forceinline__ unsigned int smem_u32(const void* p) {
    return (unsigned int)__cvta_generic_to_shared(p);
}
__device__ __forceinline__ void cpa16(unsigned int d, const void* s) {
    asm volatile("cp.async.cg.shared.global [%0], [%1], 16;" :: "r"(d), "l"(s));
}
__device__ __forceinline__ void cp_commit() {
    asm volatile("cp.async.commit_group;");
}
template<int N> __device__ __forceinline__ void cp_wait() {
    asm volatile("cp.async.wait_group %0;" :: "n"(N));
}

__global__ __launch_bounds__(TPB, 6)
void loss_fused_kernel(const float* __restrict__ pred_logits,
                       const float* __restrict__ pred_doa,
                       const float* __restrict__ target_doa,
                       const float* __restrict__ empty_weight,
                       const int*   __restrict__ target_classes,
                       float* __restrict__ out) {
    __shared__ float s_log[2][TPB * C1];   // 2 x 14336 B  (logits only)
    __shared__ float s_ew[C1];
    __shared__ float r_ce[8], r_ab[8], r_ct[8];
    __shared__ bool  s_last;

    const int tid = threadIdx.x;
    const int base = blockIdx.x * TPT;

    if (tid < C1) s_ew[tid] = empty_weight[tid];

    auto issue = [&](int buf, int tile) {
        const size_t r0 = (size_t)tile * TPB;
        const float4* gl = reinterpret_cast<const float4*>(pred_logits + r0 * C1);
        unsigned int dl = smem_u32(&s_log[buf][0]);
        cpa16(dl + (unsigned int)(tid)       * 16u, gl + tid);
        cpa16(dl + (unsigned int)(tid + 256) * 16u, gl + tid + 256);
        cpa16(dl + (unsigned int)(tid + 512) * 16u, gl + tid + 512);
        if (tid < LOG4 - 768)                                   // 128
            cpa16(dl + (unsigned int)(tid + 768) * 16u, gl + tid + 768);
    };

    // ---- prologue: prefetch logit tiles 0 and 1 ----
    issue(0, base);     cp_commit();
    issue(1, base + 1); cp_commit();

    // ---- DOA phase: coalesced float4 streams, overlapped with in-flight cp.async ----
    float acc_ab = 0.0f;
    {
        const float4* pd4 = reinterpret_cast<const float4*>(pred_doa);
        const float4* td4 = reinterpret_cast<const float4*>(target_doa);
        const int f4base = blockIdx.x * DOA4_BLK;
        #pragma unroll
        for (int u = 0; u < 4; u++) {
            int i = u * TPB + tid;
            if (u < 3 || i < DOA4_BLK) {
                int g = f4base + i;
                float4 p = __ldg(pd4 + g);
                float4 t = __ldg(td4 + g);
                int e = g * 4;
                int rA = e / 3, rB = (e + 1) / 3, rC = (e + 2) / 3, rD = (e + 3) / 3;
                float mA = (__ldg(target_classes + rA) != NUM_CLASSES) ? 1.0f : 0.0f;
                float mB = (__ldg(target_classes + rB) != NUM_CLASSES) ? 1.0f : 0.0f;
                float mC = (__ldg(target_classes + rC) != NUM_CLASSES) ? 1.0f : 0.0f;
                float mD = (__ldg(target_classes + rD) != NUM_CLASSES) ? 1.0f : 0.0f;
                acc_ab += mA * fabsf(p.x - t.x) + mB * fabsf(p.y - t.y)
                        + mC * fabsf(p.z - t.z) + mD * fabsf(p.w - t.w);
            }
        }
    }

    // ---- CE phase: double-buffered logit tiles ----
    int tg_cur = __ldg(target_classes + (size_t)base * TPB + tid);
    float acc_ce = 0.0f, acc_ct = 0.0f;

    #pragma unroll
    for (int k = 0; k < TPT; k++) {
        const int buf = k & 1;
        int tg_next = 0;
        if (k + 1 < TPT)
            tg_next = __ldg(target_classes + (size_t)(base + k + 1) * TPB + tid);

        cp_wait<1>();
        __syncthreads();

        const float2* rp = reinterpret_cast<const float2*>(&s_log[buf][tid * C1]);
        float v[C1];
        #pragma unroll
        for (int j = 0; j < C1 / 2; j++) {
            float2 p = rp[j];
            v[2 * j] = p.x; v[2 * j + 1] = p.y;
        }
        float m = fmaxf(fmaxf(fmaxf(fmaxf(v[0], v[1]), fmaxf(v[2], v[3])),
                              fmaxf(fmaxf(v[4], v[5]), fmaxf(v[6], v[7]))),
                        fmaxf(fmaxf(fmaxf(v[8], v[9]), fmaxf(v[10], v[11])),
                              fmaxf(v[12], v[13])));
        float s = 0.0f;
        #pragma unroll
        for (int j = 0; j < C1; j++) s += __expf(v[j] - m);
        float vt = s_log[buf][tid * C1 + tg_cur];      // single dynamic LDS
        acc_ce += s_ew[tg_cur] * (__logf(s) + m - vt);
        if (tg_cur != NUM_CLASSES) acc_ct += 1.0f;

        __syncthreads();                                // done reading buf
        if (k + 2 < TPT) issue(buf, base + k + 2);
        cp_commit();
        tg_cur = tg_next;
    }

    // ---- block reduction ----
    #pragma unroll
    for (int off = 16; off > 0; off >>= 1) {
        acc_ce += __shfl_down_sync(0xFFFFFFFFu, acc_ce, off);
        acc_ab += __shfl_down_sync(0xFFFFFFFFu, acc_ab, off);
        acc_ct += __shfl_down_sync(0xFFFFFFFFu, acc_ct, off);
    }
    const int lane = tid & 31, wid = tid >> 5;
    if (lane == 0) { r_ce[wid] = acc_ce; r_ab[wid] = acc_ab; r_ct[wid] = acc_ct; }
    __syncthreads();

    if (tid == 0) {
        float tce = 0.0f, tab = 0.0f, tct = 0.0f;
        #pragma unroll
        for (int w = 0; w < 8; w++) { tce += r_ce[w]; tab += r_ab[w]; tct += r_ct[w]; }
        atomicAdd(&g_acc[0], (double)tce);
        atomicAdd(&g_acc[1], (double)tab);
        atomicAdd(&g_acc[2], (double)tct);
        __threadfence();
        unsigned int ticket = atomicAdd(&g_ticket, 1u);
        s_last = (ticket == GRID - 1);
    }
    __syncthreads();

    if (s_last && tid == 0) {
        double ce = g_acc[0], ab = g_acc[1], ct = g_acc[2];
        double loss_class = ce / (double)ROWS;
        double n_elems = ct * 3.0;
        double loss_doa = (n_elems > 0.0) ? (ab / fmax(n_elems, 1.0)) : 0.0;
        out[0] = (float)(W_CLASS * loss_class + W_DOA * loss_doa);
        g_acc[0] = 0.0; g_acc[1] = 0.0; g_acc[2] = 0.0;
        __threadfence();
        g_ticket = 0u;
    }
}

extern "C" void kernel_launch(void* const* d_in, const int* in_sizes, int n_in,
                              void* d_out, int out_size) {
    const float* pred_logits    = (const float*)d_in[0];
    const float* pred_doa       = (const float*)d_in[1];
    const float* target_doa     = (const float*)d_in[2];
    const float* empty_weight   = (const float*)d_in[3];
    const int*   target_classes = (const int*)d_in[4];
    float* out = (float*)d_out;

    loss_fused_kernel<<<GRID, TPB>>>(pred_logits, pred_doa, target_doa,
                                     empty_weight, target_classes, out);
}